// round 8
// baseline (speedup 1.0000x reference)
#include <cuda_runtime.h>
#include <cstdint>

using u64 = unsigned long long;
using u32 = unsigned int;

// Problem constants
constexpr int B = 32;
constexpr int N = 131072;
constexpr int K = 1024;

// Config
constexpr int C     = 4;        // CTAs per batch (cluster)
constexpr int T     = 256;      // threads per CTA (8 warps)
constexpr int S     = N / C;    // 32768 pts per CTA slice
constexpr int CH    = 256;      // points per chunk
constexpr int NCH   = S / CH;   // 128 chunks per CTA
constexpr int CHB   = N / CH;   // 512 chunks per batch
constexpr int CELLS = 4096;     // 16^3 Morton cells per batch

// Static device scratch (allocation-free)
__device__ __align__(16) float4 g_p[B * N];     // sorted AoS: x,y,z,origidx
__device__ int   g_hist[B * CELLS];
__device__ int   g_cur[B * CELLS];
__device__ float g_bbox[B * CHB * 6];

// ---- Morton cell id (4 bits/dim) ----
__device__ __forceinline__ u32 expand3_4(u32 v) {
    return (v & 1u) | ((v & 2u) << 2) | ((v & 4u) << 4) | ((v & 8u) << 6);
}
__device__ __forceinline__ int cell_of(float x, float y, float z) {
    int ix = min(15, max(0, (int)((x + 4.5f) * (16.0f / 9.0f))));
    int iy = min(15, max(0, (int)((y + 4.5f) * (16.0f / 9.0f))));
    int iz = min(15, max(0, (int)((z + 4.5f) * (16.0f / 9.0f))));
    return (int)(expand3_4((u32)ix) | (expand3_4((u32)iy) << 1) |
                 (expand3_4((u32)iz) << 2));
}

// ---- Preprocessing ----
__global__ void zero_hist_kernel() {
    int i = blockIdx.x * blockDim.x + threadIdx.x;
    if (i < B * CELLS) g_hist[i] = 0;
}

__global__ void cell_hist_kernel(const float* __restrict__ pts) {
    int i = blockIdx.x * blockDim.x + threadIdx.x;
    if (i >= B * N) return;
    float x = pts[3 * i], y = pts[3 * i + 1], z = pts[3 * i + 2];
    atomicAdd(&g_hist[(i / N) * CELLS + cell_of(x, y, z)], 1);
}

__global__ void cell_scan_kernel() {   // exclusive scan, one CTA per batch
    __shared__ int wt[32];
    int b = blockIdx.x, t = threadIdx.x;
    int lane = t & 31, w = t >> 5;
    int v[4], s = 0;
    #pragma unroll
    for (int j = 0; j < 4; j++) { v[j] = g_hist[b * CELLS + t * 4 + j]; s += v[j]; }
    int ps = s;
    #pragma unroll
    for (int o = 1; o < 32; o <<= 1) {
        int u = __shfl_up_sync(0xffffffffu, ps, o);
        if (lane >= o) ps += u;
    }
    if (lane == 31) wt[w] = ps;
    __syncthreads();
    if (w == 0) {
        int x = wt[lane];
        #pragma unroll
        for (int o = 1; o < 32; o <<= 1) {
            int u = __shfl_up_sync(0xffffffffu, x, o);
            if (lane >= o) x += u;
        }
        wt[lane] = x;
    }
    __syncthreads();
    int run = (w > 0 ? wt[w - 1] : 0) + (ps - s);
    #pragma unroll
    for (int j = 0; j < 4; j++) { g_cur[b * CELLS + t * 4 + j] = run; run += v[j]; }
}

__global__ void scatter_kernel(const float* __restrict__ pts) {
    int i = blockIdx.x * blockDim.x + threadIdx.x;
    if (i >= B * N) return;
    int b = i / N, j = i - b * N;
    float x = pts[3 * i], y = pts[3 * i + 1], z = pts[3 * i + 2];
    int pos = atomicAdd(&g_cur[b * CELLS + cell_of(x, y, z)], 1);
    g_p[b * N + pos] = make_float4(x, y, z, __int_as_float(j));
}

__global__ void chunk_bbox_kernel() {   // one 256-thread block per chunk
    __shared__ float rmn[3][8], rmx[3][8];
    int ch = blockIdx.x, t = threadIdx.x;
    int lane = t & 31, w = t >> 5;
    float4 p = g_p[ch * CH + t];
    float mnx = p.x, mxx = p.x, mny = p.y, mxy = p.y, mnz = p.z, mxz = p.z;
    #pragma unroll
    for (int s = 16; s > 0; s >>= 1) {
        mnx = fminf(mnx, __shfl_xor_sync(0xffffffffu, mnx, s));
        mxx = fmaxf(mxx, __shfl_xor_sync(0xffffffffu, mxx, s));
        mny = fminf(mny, __shfl_xor_sync(0xffffffffu, mny, s));
        mxy = fmaxf(mxy, __shfl_xor_sync(0xffffffffu, mxy, s));
        mnz = fminf(mnz, __shfl_xor_sync(0xffffffffu, mnz, s));
        mxz = fmaxf(mxz, __shfl_xor_sync(0xffffffffu, mxz, s));
    }
    if (lane == 0) {
        rmn[0][w] = mnx; rmx[0][w] = mxx;
        rmn[1][w] = mny; rmx[1][w] = mxy;
        rmn[2][w] = mnz; rmx[2][w] = mxz;
    }
    __syncthreads();
    if (t == 0) {
        float a0 = rmn[0][0], b0 = rmx[0][0];
        float a1 = rmn[1][0], b1 = rmx[1][0];
        float a2 = rmn[2][0], b2 = rmx[2][0];
        #pragma unroll
        for (int i = 1; i < 8; i++) {
            a0 = fminf(a0, rmn[0][i]); b0 = fmaxf(b0, rmx[0][i]);
            a1 = fminf(a1, rmn[1][i]); b1 = fmaxf(b1, rmx[1][i]);
            a2 = fminf(a2, rmn[2][i]); b2 = fmaxf(b2, rmx[2][i]);
        }
        float* bb = &g_bbox[ch * 6];
        bb[0] = a0; bb[1] = b0; bb[2] = a1; bb[3] = b1; bb[4] = a2; bb[5] = b2;
    }
}

// ---- cluster / mbarrier PTX helpers ----
__device__ __forceinline__ u32 smem_u32(const void* p) {
    u32 a;
    asm("{ .reg .u64 t; cvta.to.shared.u64 t, %1; cvt.u32.u64 %0, t; }"
        : "=r"(a) : "l"(p));
    return a;
}
__device__ __forceinline__ u32 mapa_rank(u32 addr, u32 r) {
    u32 o;
    asm("mapa.shared::cluster.u32 %0, %1, %2;" : "=r"(o) : "r"(addr), "r"(r));
    return o;
}
__device__ __forceinline__ void st_cluster_u64(u32 addr, u64 v) {
    asm volatile("st.shared::cluster.b64 [%0], %1;" :: "r"(addr), "l"(v) : "memory");
}
__device__ __forceinline__ void mbar_init(u32 addr, u32 count) {
    asm volatile("mbarrier.init.shared.b64 [%0], %1;" :: "r"(addr), "r"(count) : "memory");
}
__device__ __forceinline__ void mbar_arrive_cluster(u32 addr) {
    asm volatile("mbarrier.arrive.release.cluster.shared::cluster.b64 _, [%0];"
                 :: "r"(addr) : "memory");
}
__device__ __forceinline__ void mbar_wait_cluster(u32 addr, u32 parity) {
    asm volatile(
        "{\n\t.reg .pred P;\n\t"
        "WL_%=:\n\t"
        "mbarrier.try_wait.parity.acquire.cluster.shared::cta.b64 P, [%0], %1, 0x989680;\n\t"
        "@P bra.uni WD_%=;\n\t"
        "bra.uni WL_%=;\n\t"
        "WD_%=:\n\t}"
        :: "r"(addr), "r"(parity) : "memory");
}
__device__ __forceinline__ void cluster_sync_asm() {
    asm volatile("barrier.cluster.arrive.aligned;" ::: "memory");
    asm volatile("barrier.cluster.wait.aligned;" ::: "memory");
}

// ---- SMEM layout (bytes) ----
constexpr int SM_DIST = 0;                         // S floats  = 131072
constexpr int SM_BOX  = SM_DIST + S * 4;           // NCH*6 f   =   3072
constexpr int SM_CB   = SM_BOX + NCH * 24;         // NCH u64   =   1024
constexpr int SM_CX   = SM_CB + NCH * 8;           // NCH f     =    512
constexpr int SM_CY   = SM_CX + NCH * 4;
constexpr int SM_CZ   = SM_CY + NCH * 4;
constexpr int SM_WL   = SM_CZ + NCH * 4;           // NCH u32   =    512
constexpr int SM_WC   = SM_WL + NCH * 4;           // 2 u32 +pad=     16
constexpr int SM_MBAR = SM_WC + 16;                // 2 u64     =     16
constexpr int SM_SLOT = SM_MBAR + 16;              // 2*4*24    =    192
constexpr int SMEM_TOTAL = SM_SLOT + 2 * C * 24;   // 137,440 B

__global__ void __cluster_dims__(C, 1, 1) __launch_bounds__(T, 1)
fps_kernel(const float* __restrict__ pts, const int* __restrict__ init_idx,
           float* __restrict__ out)
{
    extern __shared__ char smem[];
    float4* sd4  = (float4*)(smem + SM_DIST);
    float*  sbox = (float*)(smem + SM_BOX);
    u64*    scb  = (u64*)(smem + SM_CB);
    float*  scx  = (float*)(smem + SM_CX);
    float*  scy  = (float*)(smem + SM_CY);
    float*  scz  = (float*)(smem + SM_CZ);
    u32*    swl  = (u32*)(smem + SM_WL);
    u32*    swc  = (u32*)(smem + SM_WC);

    const u32 mbar_base = smem_u32(smem + SM_MBAR);   // mbar[ph] = base + ph*8
    const u32 slot_base = smem_u32(smem + SM_SLOT);   // slot(ph,r) = base + (ph*4+r)*24

    const int rank = blockIdx.x;    // 0..C-1 (cluster rank, cluster dims = grid.x)
    const int b    = blockIdx.y;
    const int t    = threadIdx.x;
    const int warp = t >> 5, lane = t & 31;
    const int gbase = b * N + rank * S;             // slice start in g_p
    const int bbase = (b * CHB + rank * NCH) * 6;   // slice start in g_bbox

    const float4* __restrict__ gp = g_p + gbase;

    // ---- init ----
    #pragma unroll
    for (int j = 0; j < S / (4 * T); j++)           // 32 iters: dist = INF
        sd4[t + j * T] = make_float4(1e10f, 1e10f, 1e10f, 1e10f);
    for (int i = t; i < NCH * 6; i += T) sbox[i] = g_bbox[bbase + i];
    if (t < NCH) {
        scb[t] = ((u64)__float_as_uint(1e10f)) << 32;   // forces touch at k=1
        scx[t] = 0.f; scy[t] = 0.f; scz[t] = 0.f;
    }
    if (t == 0) {
        swc[0] = 0; swc[1] = 0;
        mbar_init(mbar_base + 0, C);
        mbar_init(mbar_base + 8, C);
    }

    const int idx0 = init_idx[b];
    float lx = pts[3 * (b * N + idx0) + 0];
    float ly = pts[3 * (b * N + idx0) + 1];
    float lz = pts[3 * (b * N + idx0) + 2];
    if (rank == 0 && t == 0) {
        out[(b * K + 0) * 3 + 0] = lx;
        out[(b * K + 0) * 3 + 1] = ly;
        out[(b * K + 0) * 3 + 2] = lz;
    }
    __syncthreads();
    cluster_sync_asm();   // mbarrier inits visible before any remote arrive

    int par[2] = {0, 0};

    // ---- K-1 sequential iterations ----
    for (int k = 1; k < K; k++) {
        const int ph = k & 1;

        // phase A: reset other-parity counter; bound-check all chunks
        if (t == 0) swc[ph ^ 1] = 0;
        if (t < NCH) {
            const float* bb = &sbox[t * 6];
            float dx = fmaxf(0.0f, fmaxf(bb[0] - lx, lx - bb[1]));
            float dy = fmaxf(0.0f, fmaxf(bb[2] - ly, ly - bb[3]));
            float dz = fmaxf(0.0f, fmaxf(bb[4] - lz, lz - bb[5]));
            float lb2 = __fmaf_rn(dx, dx, __fmaf_rn(dy, dy, dz * dz));
            float cub = __uint_as_float((u32)(scb[t] >> 32));
            if (lb2 * 0.99999f < cub) {             // conservative margin
                u32 p = atomicAdd(&swc[ph], 1u);
                swl[p] = (u32)t;
            }
        }
        __syncthreads();
        const int nw = (int)swc[ph];

        // phase B: warps update touched chunks (256 pts each)
        for (int wi = warp; wi < nw; wi += T / 32) {
            int c = (int)swl[wi];
            u64 bk = 0ULL;
            float bx = 0.f, by = 0.f, bz = 0.f;
            #pragma unroll
            for (int i = 0; i < 2; i++) {
                int f = c * 64 + i * 32 + lane;     // dist float4 index
                float4 D = sd4[f];
                float* Dv = (float*)&D;
                #pragma unroll
                for (int cc = 0; cc < 4; cc++) {
                    float4 p = gp[4 * f + cc];
                    float dx = p.x - lx, dy = p.y - ly, dz = p.z - lz;
                    float d2 = __fmaf_rn(dx, dx, __fmaf_rn(dy, dy, dz * dz));
                    float nd = fminf(Dv[cc], d2);
                    Dv[cc] = nd;
                    u64 key = (((u64)__float_as_uint(nd)) << 32) |
                              (u32)(~(u32)__float_as_int(p.w));
                    if (key > bk) { bk = key; bx = p.x; by = p.y; bz = p.z; }
                }
                sd4[f] = D;
            }
            #pragma unroll
            for (int o = 16; o > 0; o >>= 1) {
                u64   ok = __shfl_xor_sync(0xffffffffu, bk, o);
                float ox = __shfl_xor_sync(0xffffffffu, bx, o);
                float oy = __shfl_xor_sync(0xffffffffu, by, o);
                float oz = __shfl_xor_sync(0xffffffffu, bz, o);
                if (ok > bk) { bk = ok; bx = ox; by = oy; bz = oz; }
            }
            if (lane == 0) {
                scb[c] = bk;
                scx[c] = bx; scy[c] = by; scz[c] = bz;
            }
        }
        __syncthreads();

        // phase C: warp0 reduces 128 chunk keys, pushes best to all ranks
        if (warp == 0) {
            u64 bk = 0ULL; int bc = 0;
            #pragma unroll
            for (int i = 0; i < NCH / 32; i++) {
                u64 e = scb[lane + 32 * i];
                if (e > bk) { bk = e; bc = lane + 32 * i; }
            }
            #pragma unroll
            for (int o = 16; o > 0; o >>= 1) {
                u64 ok = __shfl_xor_sync(0xffffffffu, bk, o);
                int oc = __shfl_xor_sync(0xffffffffu, bc, o);
                if (ok > bk) { bk = ok; bc = oc; }
            }
            if (lane == 0) {
                u64 xy = ((u64)__float_as_uint(scy[bc]) << 32) |
                         (u64)__float_as_uint(scx[bc]);
                u64 z0 = (u64)__float_as_uint(scz[bc]);
                u32 my_slot = slot_base + (u32)(ph * C + rank) * 24u;
                u32 my_mbar = mbar_base + (u32)ph * 8u;
                #pragma unroll
                for (int r = 0; r < C; r++) {
                    u32 sa = mapa_rank(my_slot, (u32)r);
                    u32 ma = mapa_rank(my_mbar, (u32)r);
                    st_cluster_u64(sa +  0, bk);
                    st_cluster_u64(sa +  8, xy);
                    st_cluster_u64(sa + 16, z0);
                    mbar_arrive_cluster(ma);   // release: orders the 3 stores
                }
            }
        }

        // all threads: wait for all 4 ranks' arrivals, then pick winner
        mbar_wait_cluster(mbar_base + (u32)ph * 8u, (u32)par[ph]);
        par[ph] ^= 1;

        u64 gb = 0ULL; float nx = 0.f, ny = 0.f, nz = 0.f;
        #pragma unroll
        for (int r = 0; r < C; r++) {
            const char* sp = smem + SM_SLOT + (ph * C + r) * 24;
            u64 key = *(const u64*)(sp + 0);
            u64 xy  = *(const u64*)(sp + 8);
            u64 z0  = *(const u64*)(sp + 16);
            if (key > gb) {
                gb = key;
                nx = __uint_as_float((u32)(xy & 0xffffffffull));
                ny = __uint_as_float((u32)(xy >> 32));
                nz = __uint_as_float((u32)(z0 & 0xffffffffull));
            }
        }
        lx = nx; ly = ny; lz = nz;

        if (rank == 0 && t == 0) {
            out[(b * K + k) * 3 + 0] = lx;
            out[(b * K + k) * 3 + 1] = ly;
            out[(b * K + k) * 3 + 2] = lz;
        }
    }

    cluster_sync_asm();   // keep SMEM alive until all peer traffic retired
}

extern "C" void kernel_launch(void* const* d_in, const int* in_sizes, int n_in,
                              void* d_out, int out_size) {
    const float* pts  = (const float*)d_in[0];
    const int*   init = (const int*)d_in[1];
    float*       out  = (float*)d_out;

    cudaFuncSetAttribute(fps_kernel,
                         cudaFuncAttributeMaxDynamicSharedMemorySize, SMEM_TOTAL);

    const int tot = B * N;
    zero_hist_kernel<<<(B * CELLS + 255) / 256, 256>>>();
    cell_hist_kernel<<<(tot + 255) / 256, 256>>>(pts);
    cell_scan_kernel<<<B, 1024>>>();
    scatter_kernel<<<(tot + 255) / 256, 256>>>(pts);
    chunk_bbox_kernel<<<B * CHB, 256>>>();

    dim3 grid(C, B, 1);
    fps_kernel<<<grid, T, SMEM_TOTAL>>>(pts, init, out);
}

// round 9
// speedup vs baseline: 1.2693x; 1.2693x over previous
#include <cuda_runtime.h>
#include <cstdint>

using u64 = unsigned long long;
using u32 = unsigned int;

// Problem constants
constexpr int B = 32;
constexpr int N = 131072;
constexpr int K = 1024;

// Config
constexpr int C     = 4;        // CTAs per batch (cluster)
constexpr int T     = 512;      // threads per CTA (16 warps)
constexpr int S     = N / C;    // 32768 pts per CTA slice
constexpr int CH    = 256;      // points per chunk
constexpr int NCH   = S / CH;   // 128 chunks per CTA
constexpr int CHB   = N / CH;   // 512 chunks per batch
constexpr int CELLS = 4096;     // 16^3 Morton cells per batch

// Static device scratch (allocation-free)
__device__ __align__(16) float4 g_tmp[B * N];  // scatter target (AoS)
__device__ __align__(16) float  g_x[B * N];    // sorted SoA
__device__ __align__(16) float  g_y[B * N];
__device__ __align__(16) float  g_z[B * N];
__device__ __align__(16) int    g_i[B * N];    // original within-batch index
__device__ int   g_hist[B * CELLS];
__device__ int   g_cur[B * CELLS];
__device__ float g_bbox[B * CHB * 6];

// ---- Morton cell id (4 bits/dim) ----
__device__ __forceinline__ u32 expand3_4(u32 v) {
    return (v & 1u) | ((v & 2u) << 2) | ((v & 4u) << 4) | ((v & 8u) << 6);
}
__device__ __forceinline__ int cell_of(float x, float y, float z) {
    int ix = min(15, max(0, (int)((x + 4.5f) * (16.0f / 9.0f))));
    int iy = min(15, max(0, (int)((y + 4.5f) * (16.0f / 9.0f))));
    int iz = min(15, max(0, (int)((z + 4.5f) * (16.0f / 9.0f))));
    return (int)(expand3_4((u32)ix) | (expand3_4((u32)iy) << 1) |
                 (expand3_4((u32)iz) << 2));
}

// ---- Preprocessing ----
__global__ void zero_hist_kernel() {
    int i = blockIdx.x * blockDim.x + threadIdx.x;
    if (i < B * CELLS) g_hist[i] = 0;
}

__global__ void cell_hist_kernel(const float* __restrict__ pts) {
    int i = blockIdx.x * blockDim.x + threadIdx.x;
    if (i >= B * N) return;
    float x = pts[3 * i], y = pts[3 * i + 1], z = pts[3 * i + 2];
    atomicAdd(&g_hist[(i / N) * CELLS + cell_of(x, y, z)], 1);
}

__global__ void cell_scan_kernel() {   // exclusive scan, one CTA per batch
    __shared__ int wt[32];
    int b = blockIdx.x, t = threadIdx.x;
    int lane = t & 31, w = t >> 5;
    int v[4], s = 0;
    #pragma unroll
    for (int j = 0; j < 4; j++) { v[j] = g_hist[b * CELLS + t * 4 + j]; s += v[j]; }
    int ps = s;
    #pragma unroll
    for (int o = 1; o < 32; o <<= 1) {
        int u = __shfl_up_sync(0xffffffffu, ps, o);
        if (lane >= o) ps += u;
    }
    if (lane == 31) wt[w] = ps;
    __syncthreads();
    if (w == 0) {
        int x = wt[lane];
        #pragma unroll
        for (int o = 1; o < 32; o <<= 1) {
            int u = __shfl_up_sync(0xffffffffu, x, o);
            if (lane >= o) x += u;
        }
        wt[lane] = x;
    }
    __syncthreads();
    int run = (w > 0 ? wt[w - 1] : 0) + (ps - s);
    #pragma unroll
    for (int j = 0; j < 4; j++) { g_cur[b * CELLS + t * 4 + j] = run; run += v[j]; }
}

__global__ void scatter_kernel(const float* __restrict__ pts) {
    int i = blockIdx.x * blockDim.x + threadIdx.x;
    if (i >= B * N) return;
    int b = i / N, j = i - b * N;
    float x = pts[3 * i], y = pts[3 * i + 1], z = pts[3 * i + 2];
    int pos = atomicAdd(&g_cur[b * CELLS + cell_of(x, y, z)], 1);
    g_tmp[b * N + pos] = make_float4(x, y, z, __int_as_float(j));  // one STG.128
}

__global__ void repack_kernel() {      // AoS -> SoA, fully coalesced
    int i = blockIdx.x * blockDim.x + threadIdx.x;
    if (i >= B * N) return;
    float4 p = g_tmp[i];
    g_x[i] = p.x; g_y[i] = p.y; g_z[i] = p.z; g_i[i] = __float_as_int(p.w);
}

__global__ void chunk_bbox_kernel() {   // one 256-thread block per chunk
    __shared__ float rmn[3][8], rmx[3][8];
    int ch = blockIdx.x, t = threadIdx.x;
    int lane = t & 31, w = t >> 5;
    int o = ch * CH + t;
    float x = g_x[o], y = g_y[o], z = g_z[o];
    float mnx = x, mxx = x, mny = y, mxy = y, mnz = z, mxz = z;
    #pragma unroll
    for (int s = 16; s > 0; s >>= 1) {
        mnx = fminf(mnx, __shfl_xor_sync(0xffffffffu, mnx, s));
        mxx = fmaxf(mxx, __shfl_xor_sync(0xffffffffu, mxx, s));
        mny = fminf(mny, __shfl_xor_sync(0xffffffffu, mny, s));
        mxy = fmaxf(mxy, __shfl_xor_sync(0xffffffffu, mxy, s));
        mnz = fminf(mnz, __shfl_xor_sync(0xffffffffu, mnz, s));
        mxz = fmaxf(mxz, __shfl_xor_sync(0xffffffffu, mxz, s));
    }
    if (lane == 0) {
        rmn[0][w] = mnx; rmx[0][w] = mxx;
        rmn[1][w] = mny; rmx[1][w] = mxy;
        rmn[2][w] = mnz; rmx[2][w] = mxz;
    }
    __syncthreads();
    if (t == 0) {
        float a0 = rmn[0][0], b0 = rmx[0][0];
        float a1 = rmn[1][0], b1 = rmx[1][0];
        float a2 = rmn[2][0], b2 = rmx[2][0];
        #pragma unroll
        for (int i = 1; i < 8; i++) {
            a0 = fminf(a0, rmn[0][i]); b0 = fmaxf(b0, rmx[0][i]);
            a1 = fminf(a1, rmn[1][i]); b1 = fmaxf(b1, rmx[1][i]);
            a2 = fminf(a2, rmn[2][i]); b2 = fmaxf(b2, rmx[2][i]);
        }
        float* bb = &g_bbox[ch * 6];
        bb[0] = a0; bb[1] = b0; bb[2] = a1; bb[3] = b1; bb[4] = a2; bb[5] = b2;
    }
}

// ---- cluster / mbarrier PTX helpers ----
__device__ __forceinline__ u32 smem_u32(const void* p) {
    u32 a;
    asm("{ .reg .u64 t; cvta.to.shared.u64 t, %1; cvt.u32.u64 %0, t; }"
        : "=r"(a) : "l"(p));
    return a;
}
__device__ __forceinline__ u32 mapa_rank(u32 addr, u32 r) {
    u32 o;
    asm("mapa.shared::cluster.u32 %0, %1, %2;" : "=r"(o) : "r"(addr), "r"(r));
    return o;
}
__device__ __forceinline__ void st_cluster_u64(u32 addr, u64 v) {
    asm volatile("st.shared::cluster.b64 [%0], %1;" :: "r"(addr), "l"(v) : "memory");
}
__device__ __forceinline__ void mbar_init(u32 addr, u32 count) {
    asm volatile("mbarrier.init.shared.b64 [%0], %1;" :: "r"(addr), "r"(count) : "memory");
}
__device__ __forceinline__ void mbar_arrive_cluster(u32 addr) {
    asm volatile("mbarrier.arrive.release.cluster.shared::cluster.b64 _, [%0];"
                 :: "r"(addr) : "memory");
}
__device__ __forceinline__ void mbar_wait_cluster(u32 addr, u32 parity) {
    asm volatile(
        "{\n\t.reg .pred P;\n\t"
        "WL_%=:\n\t"
        "mbarrier.try_wait.parity.acquire.cluster.shared::cta.b64 P, [%0], %1, 0x989680;\n\t"
        "@P bra.uni WD_%=;\n\t"
        "bra.uni WL_%=;\n\t"
        "WD_%=:\n\t}"
        :: "r"(addr), "r"(parity) : "memory");
}
__device__ __forceinline__ void cluster_sync_asm() {
    asm volatile("barrier.cluster.arrive.aligned;" ::: "memory");
    asm volatile("barrier.cluster.wait.aligned;" ::: "memory");
}

// ---- SMEM layout (bytes) ----
constexpr int SM_DIST = 0;                         // S floats  = 131072
constexpr int SM_BOX  = SM_DIST + S * 4;           // NCH*6 f   =   3072
constexpr int SM_CB   = SM_BOX + NCH * 24;         // NCH u64   =   1024
constexpr int SM_CX   = SM_CB + NCH * 8;           // NCH f
constexpr int SM_CY   = SM_CX + NCH * 4;
constexpr int SM_CZ   = SM_CY + NCH * 4;
constexpr int SM_WL   = SM_CZ + NCH * 4;           // NCH u32
constexpr int SM_WC   = SM_WL + NCH * 4;           // 2 u32 + pad
constexpr int SM_MBAR = SM_WC + 16;                // 2 u64
constexpr int SM_SLOT = SM_MBAR + 16;              // 2*4*24
constexpr int SMEM_TOTAL = SM_SLOT + 2 * C * 24;   // 137,440 B

__global__ void __cluster_dims__(C, 1, 1) __launch_bounds__(T, 1)
fps_kernel(const float* __restrict__ pts, const int* __restrict__ init_idx,
           float* __restrict__ out)
{
    extern __shared__ char smem[];
    float4* sd4  = (float4*)(smem + SM_DIST);
    float*  sbox = (float*)(smem + SM_BOX);
    u64*    scb  = (u64*)(smem + SM_CB);
    float*  scx  = (float*)(smem + SM_CX);
    float*  scy  = (float*)(smem + SM_CY);
    float*  scz  = (float*)(smem + SM_CZ);
    u32*    swl  = (u32*)(smem + SM_WL);
    u32*    swc  = (u32*)(smem + SM_WC);

    const u32 mbar_base = smem_u32(smem + SM_MBAR);
    const u32 slot_base = smem_u32(smem + SM_SLOT);

    const int rank = blockIdx.x;
    const int b    = blockIdx.y;
    const int t    = threadIdx.x;
    const int warp = t >> 5, lane = t & 31;
    const int gbase = b * N + rank * S;
    const int bbase = (b * CHB + rank * NCH) * 6;

    const float4* __restrict__ gx4 = (const float4*)(g_x + gbase);
    const float4* __restrict__ gy4 = (const float4*)(g_y + gbase);
    const float4* __restrict__ gz4 = (const float4*)(g_z + gbase);
    const int4*   __restrict__ gi4 = (const int4*)(g_i + gbase);

    // ---- init ----
    #pragma unroll
    for (int j = 0; j < S / (4 * T); j++)
        sd4[t + j * T] = make_float4(1e10f, 1e10f, 1e10f, 1e10f);
    for (int i = t; i < NCH * 6; i += T) sbox[i] = g_bbox[bbase + i];
    if (t < NCH) {
        scb[t] = ((u64)__float_as_uint(1e10f)) << 32;   // forces touch at k=1
        scx[t] = 0.f; scy[t] = 0.f; scz[t] = 0.f;
    }
    if (t == 0) {
        swc[0] = 0; swc[1] = 0;
        mbar_init(mbar_base + 0, C);
        mbar_init(mbar_base + 8, C);
    }

    const int idx0 = init_idx[b];
    float lx = pts[3 * (b * N + idx0) + 0];
    float ly = pts[3 * (b * N + idx0) + 1];
    float lz = pts[3 * (b * N + idx0) + 2];
    if (rank == 0 && t == 0) {
        out[(b * K + 0) * 3 + 0] = lx;
        out[(b * K + 0) * 3 + 1] = ly;
        out[(b * K + 0) * 3 + 2] = lz;
    }
    __syncthreads();
    cluster_sync_asm();   // mbarrier inits visible before any remote arrive

    int par[2] = {0, 0};

    // ---- K-1 sequential iterations ----
    for (int k = 1; k < K; k++) {
        const int ph = k & 1;

        // phase A: reset other-parity counter; bound-check all chunks
        if (t == 0) swc[ph ^ 1] = 0;
        if (t < NCH) {
            const float* bb = &sbox[t * 6];
            float dx = fmaxf(0.0f, fmaxf(bb[0] - lx, lx - bb[1]));
            float dy = fmaxf(0.0f, fmaxf(bb[2] - ly, ly - bb[3]));
            float dz = fmaxf(0.0f, fmaxf(bb[4] - lz, lz - bb[5]));
            float lb2 = __fmaf_rn(dx, dx, __fmaf_rn(dy, dy, dz * dz));
            float cub = __uint_as_float((u32)(scb[t] >> 32));
            if (lb2 * 0.99999f < cub) {             // conservative margin
                u32 p = atomicAdd(&swc[ph], 1u);
                swl[p] = (u32)t;
            }
        }
        __syncthreads();
        const int nw = (int)swc[ph];

        // phase B: warps update touched chunks (256 pts, SoA coalesced)
        for (int wi = warp; wi < nw; wi += T / 32) {
            int c = (int)swl[wi];
            u64 bk = 0ULL;
            float bx = 0.f, by = 0.f, bz = 0.f;
            #pragma unroll
            for (int i = 0; i < 2; i++) {
                int f = c * 64 + i * 32 + lane;     // float4 index, coalesced
                float4 X = gx4[f];
                float4 Y = gy4[f];
                float4 Z = gz4[f];
                int4   I = gi4[f];
                float4 D = sd4[f];
                const float* Xv = (const float*)&X;
                const float* Yv = (const float*)&Y;
                const float* Zv = (const float*)&Z;
                const int*   Iv = (const int*)&I;
                float* Dv = (float*)&D;
                #pragma unroll
                for (int cc = 0; cc < 4; cc++) {
                    float dx = Xv[cc] - lx, dy = Yv[cc] - ly, dz = Zv[cc] - lz;
                    float d2 = __fmaf_rn(dx, dx, __fmaf_rn(dy, dy, dz * dz));
                    float nd = fminf(Dv[cc], d2);
                    Dv[cc] = nd;
                    u64 key = (((u64)__float_as_uint(nd)) << 32) |
                              (u32)(~(u32)Iv[cc]);
                    if (key > bk) { bk = key; bx = Xv[cc]; by = Yv[cc]; bz = Zv[cc]; }
                }
                sd4[f] = D;
            }
            #pragma unroll
            for (int o = 16; o > 0; o >>= 1) {
                u64   ok = __shfl_xor_sync(0xffffffffu, bk, o);
                float ox = __shfl_xor_sync(0xffffffffu, bx, o);
                float oy = __shfl_xor_sync(0xffffffffu, by, o);
                float oz = __shfl_xor_sync(0xffffffffu, bz, o);
                if (ok > bk) { bk = ok; bx = ox; by = oy; bz = oz; }
            }
            if (lane == 0) {
                scb[c] = bk;
                scx[c] = bx; scy[c] = by; scz[c] = bz;
            }
        }
        __syncthreads();

        // phase C: warp0 reduces chunk keys, pushes best to all ranks
        if (warp == 0) {
            u64 bk = 0ULL; int bc = 0;
            #pragma unroll
            for (int i = 0; i < NCH / 32; i++) {
                u64 e = scb[lane + 32 * i];
                if (e > bk) { bk = e; bc = lane + 32 * i; }
            }
            #pragma unroll
            for (int o = 16; o > 0; o >>= 1) {
                u64 ok = __shfl_xor_sync(0xffffffffu, bk, o);
                int oc = __shfl_xor_sync(0xffffffffu, bc, o);
                if (ok > bk) { bk = ok; bc = oc; }
            }
            if (lane == 0) {
                u64 xy = ((u64)__float_as_uint(scy[bc]) << 32) |
                         (u64)__float_as_uint(scx[bc]);
                u64 z0 = (u64)__float_as_uint(scz[bc]);
                u32 my_slot = slot_base + (u32)(ph * C + rank) * 24u;
                u32 my_mbar = mbar_base + (u32)ph * 8u;
                #pragma unroll
                for (int r = 0; r < C; r++) {
                    u32 sa = mapa_rank(my_slot, (u32)r);
                    u32 ma = mapa_rank(my_mbar, (u32)r);
                    st_cluster_u64(sa +  0, bk);
                    st_cluster_u64(sa +  8, xy);
                    st_cluster_u64(sa + 16, z0);
                    mbar_arrive_cluster(ma);   // release: orders the 3 stores
                }
            }
        }

        // all threads: wait for all 4 ranks' arrivals, then pick winner
        mbar_wait_cluster(mbar_base + (u32)ph * 8u, (u32)par[ph]);
        par[ph] ^= 1;

        u64 gb = 0ULL; float nx = 0.f, ny = 0.f, nz = 0.f;
        #pragma unroll
        for (int r = 0; r < C; r++) {
            const char* sp = smem + SM_SLOT + (ph * C + r) * 24;
            u64 key = *(const u64*)(sp + 0);
            u64 xy  = *(const u64*)(sp + 8);
            u64 z0  = *(const u64*)(sp + 16);
            if (key > gb) {
                gb = key;
                nx = __uint_as_float((u32)(xy & 0xffffffffull));
                ny = __uint_as_float((u32)(xy >> 32));
                nz = __uint_as_float((u32)(z0 & 0xffffffffull));
            }
        }
        lx = nx; ly = ny; lz = nz;

        if (rank == 0 && t == 0) {
            out[(b * K + k) * 3 + 0] = lx;
            out[(b * K + k) * 3 + 1] = ly;
            out[(b * K + k) * 3 + 2] = lz;
        }
    }

    cluster_sync_asm();   // keep SMEM alive until all peer traffic retired
}

extern "C" void kernel_launch(void* const* d_in, const int* in_sizes, int n_in,
                              void* d_out, int out_size) {
    const float* pts  = (const float*)d_in[0];
    const int*   init = (const int*)d_in[1];
    float*       out  = (float*)d_out;

    cudaFuncSetAttribute(fps_kernel,
                         cudaFuncAttributeMaxDynamicSharedMemorySize, SMEM_TOTAL);

    const int tot = B * N;
    zero_hist_kernel<<<(B * CELLS + 255) / 256, 256>>>();
    cell_hist_kernel<<<(tot + 255) / 256, 256>>>(pts);
    cell_scan_kernel<<<B, 1024>>>();
    scatter_kernel<<<(tot + 255) / 256, 256>>>(pts);
    repack_kernel<<<(tot + 255) / 256, 256>>>();
    chunk_bbox_kernel<<<B * CHB, 256>>>();

    dim3 grid(C, B, 1);
    fps_kernel<<<grid, T, SMEM_TOTAL>>>(pts, init, out);
}

// round 10
// speedup vs baseline: 1.3150x; 1.0360x over previous
#include <cuda_runtime.h>
#include <cstdint>

using u64 = unsigned long long;
using u32 = unsigned int;

// Problem constants
constexpr int B = 32;
constexpr int N = 131072;
constexpr int K = 1024;

// Config
constexpr int C     = 4;        // CTAs per batch (cluster)
constexpr int T     = 1024;     // threads per CTA (32 warps)
constexpr int S     = N / C;    // 32768 pts per CTA slice
constexpr int CH    = 128;      // points per chunk (1 float4 round per warp)
constexpr int NCH   = S / CH;   // 256 chunks per CTA
constexpr int CHB   = N / CH;   // 1024 chunks per batch
constexpr int CELLS = 4096;     // 16^3 Morton cells per batch

// Static device scratch (allocation-free)
__device__ __align__(16) float4 g_tmp[B * N];  // scatter target (AoS)
__device__ __align__(16) float  g_x[B * N];    // sorted SoA
__device__ __align__(16) float  g_y[B * N];
__device__ __align__(16) float  g_z[B * N];
__device__ __align__(16) int    g_i[B * N];    // original within-batch index
__device__ int   g_hist[B * CELLS];
__device__ int   g_cur[B * CELLS];
__device__ float g_bbox[B * CHB * 6];

// ---- Morton cell id (4 bits/dim) ----
__device__ __forceinline__ u32 expand3_4(u32 v) {
    return (v & 1u) | ((v & 2u) << 2) | ((v & 4u) << 4) | ((v & 8u) << 6);
}
__device__ __forceinline__ int cell_of(float x, float y, float z) {
    int ix = min(15, max(0, (int)((x + 4.5f) * (16.0f / 9.0f))));
    int iy = min(15, max(0, (int)((y + 4.5f) * (16.0f / 9.0f))));
    int iz = min(15, max(0, (int)((z + 4.5f) * (16.0f / 9.0f))));
    return (int)(expand3_4((u32)ix) | (expand3_4((u32)iy) << 1) |
                 (expand3_4((u32)iz) << 2));
}

// ---- Preprocessing ----
__global__ void zero_hist_kernel() {
    int i = blockIdx.x * blockDim.x + threadIdx.x;
    if (i < B * CELLS) g_hist[i] = 0;
}

__global__ void cell_hist_kernel(const float* __restrict__ pts) {
    int i = blockIdx.x * blockDim.x + threadIdx.x;
    if (i >= B * N) return;
    float x = pts[3 * i], y = pts[3 * i + 1], z = pts[3 * i + 2];
    atomicAdd(&g_hist[(i / N) * CELLS + cell_of(x, y, z)], 1);
}

__global__ void cell_scan_kernel() {   // exclusive scan, one CTA per batch
    __shared__ int wt[32];
    int b = blockIdx.x, t = threadIdx.x;
    int lane = t & 31, w = t >> 5;
    int v[4], s = 0;
    #pragma unroll
    for (int j = 0; j < 4; j++) { v[j] = g_hist[b * CELLS + t * 4 + j]; s += v[j]; }
    int ps = s;
    #pragma unroll
    for (int o = 1; o < 32; o <<= 1) {
        int u = __shfl_up_sync(0xffffffffu, ps, o);
        if (lane >= o) ps += u;
    }
    if (lane == 31) wt[w] = ps;
    __syncthreads();
    if (w == 0) {
        int x = wt[lane];
        #pragma unroll
        for (int o = 1; o < 32; o <<= 1) {
            int u = __shfl_up_sync(0xffffffffu, x, o);
            if (lane >= o) x += u;
        }
        wt[lane] = x;
    }
    __syncthreads();
    int run = (w > 0 ? wt[w - 1] : 0) + (ps - s);
    #pragma unroll
    for (int j = 0; j < 4; j++) { g_cur[b * CELLS + t * 4 + j] = run; run += v[j]; }
}

__global__ void scatter_kernel(const float* __restrict__ pts) {
    int i = blockIdx.x * blockDim.x + threadIdx.x;
    if (i >= B * N) return;
    int b = i / N, j = i - b * N;
    float x = pts[3 * i], y = pts[3 * i + 1], z = pts[3 * i + 2];
    int pos = atomicAdd(&g_cur[b * CELLS + cell_of(x, y, z)], 1);
    g_tmp[b * N + pos] = make_float4(x, y, z, __int_as_float(j));  // one STG.128
}

__global__ void repack_kernel() {      // AoS -> SoA, fully coalesced
    int i = blockIdx.x * blockDim.x + threadIdx.x;
    if (i >= B * N) return;
    float4 p = g_tmp[i];
    g_x[i] = p.x; g_y[i] = p.y; g_z[i] = p.z; g_i[i] = __float_as_int(p.w);
}

__global__ void chunk_bbox_kernel() {   // one 128-thread block per chunk
    __shared__ float rmn[3][4], rmx[3][4];
    int ch = blockIdx.x, t = threadIdx.x;
    int lane = t & 31, w = t >> 5;
    int o = ch * CH + t;
    float x = g_x[o], y = g_y[o], z = g_z[o];
    float mnx = x, mxx = x, mny = y, mxy = y, mnz = z, mxz = z;
    #pragma unroll
    for (int s = 16; s > 0; s >>= 1) {
        mnx = fminf(mnx, __shfl_xor_sync(0xffffffffu, mnx, s));
        mxx = fmaxf(mxx, __shfl_xor_sync(0xffffffffu, mxx, s));
        mny = fminf(mny, __shfl_xor_sync(0xffffffffu, mny, s));
        mxy = fmaxf(mxy, __shfl_xor_sync(0xffffffffu, mxy, s));
        mnz = fminf(mnz, __shfl_xor_sync(0xffffffffu, mnz, s));
        mxz = fmaxf(mxz, __shfl_xor_sync(0xffffffffu, mxz, s));
    }
    if (lane == 0) {
        rmn[0][w] = mnx; rmx[0][w] = mxx;
        rmn[1][w] = mny; rmx[1][w] = mxy;
        rmn[2][w] = mnz; rmx[2][w] = mxz;
    }
    __syncthreads();
    if (t == 0) {
        float a0 = rmn[0][0], b0 = rmx[0][0];
        float a1 = rmn[1][0], b1 = rmx[1][0];
        float a2 = rmn[2][0], b2 = rmx[2][0];
        #pragma unroll
        for (int i = 1; i < 4; i++) {
            a0 = fminf(a0, rmn[0][i]); b0 = fmaxf(b0, rmx[0][i]);
            a1 = fminf(a1, rmn[1][i]); b1 = fmaxf(b1, rmx[1][i]);
            a2 = fminf(a2, rmn[2][i]); b2 = fmaxf(b2, rmx[2][i]);
        }
        float* bb = &g_bbox[ch * 6];
        bb[0] = a0; bb[1] = b0; bb[2] = a1; bb[3] = b1; bb[4] = a2; bb[5] = b2;
    }
}

// ---- cluster / mbarrier PTX helpers ----
__device__ __forceinline__ u32 smem_u32(const void* p) {
    u32 a;
    asm("{ .reg .u64 t; cvta.to.shared.u64 t, %1; cvt.u32.u64 %0, t; }"
        : "=r"(a) : "l"(p));
    return a;
}
__device__ __forceinline__ u32 mapa_rank(u32 addr, u32 r) {
    u32 o;
    asm("mapa.shared::cluster.u32 %0, %1, %2;" : "=r"(o) : "r"(addr), "r"(r));
    return o;
}
__device__ __forceinline__ void st_cluster_u64(u32 addr, u64 v) {
    asm volatile("st.shared::cluster.b64 [%0], %1;" :: "r"(addr), "l"(v) : "memory");
}
__device__ __forceinline__ void mbar_init(u32 addr, u32 count) {
    asm volatile("mbarrier.init.shared.b64 [%0], %1;" :: "r"(addr), "r"(count) : "memory");
}
__device__ __forceinline__ void mbar_arrive_cluster(u32 addr) {
    asm volatile("mbarrier.arrive.release.cluster.shared::cluster.b64 _, [%0];"
                 :: "r"(addr) : "memory");
}
__device__ __forceinline__ void mbar_wait_cluster(u32 addr, u32 parity) {
    asm volatile(
        "{\n\t.reg .pred P;\n\t"
        "WL_%=:\n\t"
        "mbarrier.try_wait.parity.acquire.cluster.shared::cta.b64 P, [%0], %1, 0x989680;\n\t"
        "@P bra.uni WD_%=;\n\t"
        "bra.uni WL_%=;\n\t"
        "WD_%=:\n\t}"
        :: "r"(addr), "r"(parity) : "memory");
}
__device__ __forceinline__ void cluster_sync_asm() {
    asm volatile("barrier.cluster.arrive.aligned;" ::: "memory");
    asm volatile("barrier.cluster.wait.aligned;" ::: "memory");
}

// ---- SMEM layout (bytes) ----
constexpr int SM_DIST = 0;                         // S floats  = 131072
constexpr int SM_BOX  = SM_DIST + S * 4;           // NCH*6 f   =   6144
constexpr int SM_CB   = SM_BOX + NCH * 24;         // NCH u64   =   2048
constexpr int SM_CX   = SM_CB + NCH * 8;           // NCH f     =   1024
constexpr int SM_CY   = SM_CX + NCH * 4;
constexpr int SM_CZ   = SM_CY + NCH * 4;
constexpr int SM_WL   = SM_CZ + NCH * 4;           // NCH u32   =   1024
constexpr int SM_WC   = SM_WL + NCH * 4;           // 2 u32 + pad
constexpr int SM_MBAR = SM_WC + 16;                // 2 u64
constexpr int SM_SLOT = SM_MBAR + 16;              // 2*4*24
constexpr int SM_SBC  = SM_SLOT + 2 * C * 24;      // winner bcast (x,y,z)
constexpr int SMEM_TOTAL = SM_SBC + 16;            // ~142.6 KB

__global__ void __cluster_dims__(C, 1, 1) __launch_bounds__(T, 1)
fps_kernel(const float* __restrict__ pts, const int* __restrict__ init_idx,
           float* __restrict__ out)
{
    extern __shared__ char smem[];
    float4* sd4  = (float4*)(smem + SM_DIST);
    float*  sbox = (float*)(smem + SM_BOX);
    u64*    scb  = (u64*)(smem + SM_CB);
    float*  scx  = (float*)(smem + SM_CX);
    float*  scy  = (float*)(smem + SM_CY);
    float*  scz  = (float*)(smem + SM_CZ);
    u32*    swl  = (u32*)(smem + SM_WL);
    u32*    swc  = (u32*)(smem + SM_WC);
    float*  sbc  = (float*)(smem + SM_SBC);

    const u32 mbar_base = smem_u32(smem + SM_MBAR);
    const u32 slot_base = smem_u32(smem + SM_SLOT);

    const int rank = blockIdx.x;
    const int b    = blockIdx.y;
    const int t    = threadIdx.x;
    const int warp = t >> 5, lane = t & 31;
    const int gbase = b * N + rank * S;
    const int bbase = (b * CHB + rank * NCH) * 6;

    const float4* __restrict__ gx4 = (const float4*)(g_x + gbase);
    const float4* __restrict__ gy4 = (const float4*)(g_y + gbase);
    const float4* __restrict__ gz4 = (const float4*)(g_z + gbase);
    const int4*   __restrict__ gi4 = (const int4*)(g_i + gbase);

    // ---- init ----
    #pragma unroll
    for (int j = 0; j < S / (4 * T); j++)
        sd4[t + j * T] = make_float4(1e10f, 1e10f, 1e10f, 1e10f);
    for (int i = t; i < NCH * 6; i += T) sbox[i] = g_bbox[bbase + i];
    if (t < NCH) {
        scb[t] = ((u64)__float_as_uint(1e10f)) << 32;   // forces touch at k=1
        scx[t] = 0.f; scy[t] = 0.f; scz[t] = 0.f;
    }
    if (t == 0) {
        swc[0] = 0; swc[1] = 0;
        mbar_init(mbar_base + 0, C);
        mbar_init(mbar_base + 8, C);
        const int idx0 = init_idx[b];
        float lx = pts[3 * (b * N + idx0) + 0];
        float ly = pts[3 * (b * N + idx0) + 1];
        float lz = pts[3 * (b * N + idx0) + 2];
        sbc[0] = lx; sbc[1] = ly; sbc[2] = lz;
        if (rank == 0) {
            out[(b * K + 0) * 3 + 0] = lx;
            out[(b * K + 0) * 3 + 1] = ly;
            out[(b * K + 0) * 3 + 2] = lz;
        }
    }
    __syncthreads();
    cluster_sync_asm();   // mbarrier inits visible before any remote arrive

    int par[2] = {0, 0};

    // ---- K-1 sequential iterations ----
    for (int k = 1; k < K; k++) {
        const int ph = k & 1;

        // all threads read the current selected point (written by warp0)
        const float lx = sbc[0], ly = sbc[1], lz = sbc[2];

        // phase A: reset other-parity counter; bound-check all chunks
        if (t == 0) swc[ph ^ 1] = 0;
        if (t < NCH) {
            const float* bb = &sbox[t * 6];
            float dx = fmaxf(0.0f, fmaxf(bb[0] - lx, lx - bb[1]));
            float dy = fmaxf(0.0f, fmaxf(bb[2] - ly, ly - bb[3]));
            float dz = fmaxf(0.0f, fmaxf(bb[4] - lz, lz - bb[5]));
            float lb2 = __fmaf_rn(dx, dx, __fmaf_rn(dy, dy, dz * dz));
            float cub = __uint_as_float((u32)(scb[t] >> 32));
            if (lb2 * 0.99999f < cub) {             // conservative margin
                u32 p = atomicAdd(&swc[ph], 1u);
                swl[p] = (u32)t;
            }
        }
        __syncthreads();
        const int nw = (int)swc[ph];

        // phase B: one warp per touched chunk (128 pts, SoA coalesced)
        for (int wi = warp; wi < nw; wi += T / 32) {
            int c = (int)swl[wi];
            int f = c * 32 + lane;                  // float4 index, coalesced
            float4 X = gx4[f];
            float4 Y = gy4[f];
            float4 Z = gz4[f];
            int4   I = gi4[f];
            float4 D = sd4[f];
            const float* Xv = (const float*)&X;
            const float* Yv = (const float*)&Y;
            const float* Zv = (const float*)&Z;
            const int*   Iv = (const int*)&I;
            float* Dv = (float*)&D;
            u64 bk = 0ULL;
            float bx = 0.f, by = 0.f, bz = 0.f;
            #pragma unroll
            for (int cc = 0; cc < 4; cc++) {
                float dx = Xv[cc] - lx, dy = Yv[cc] - ly, dz = Zv[cc] - lz;
                float d2 = __fmaf_rn(dx, dx, __fmaf_rn(dy, dy, dz * dz));
                float nd = fminf(Dv[cc], d2);
                Dv[cc] = nd;
                u64 key = (((u64)__float_as_uint(nd)) << 32) |
                          (u32)(~(u32)Iv[cc]);
                if (key > bk) { bk = key; bx = Xv[cc]; by = Yv[cc]; bz = Zv[cc]; }
            }
            sd4[f] = D;
            #pragma unroll
            for (int o = 16; o > 0; o >>= 1) {
                u64   ok = __shfl_xor_sync(0xffffffffu, bk, o);
                float ox = __shfl_xor_sync(0xffffffffu, bx, o);
                float oy = __shfl_xor_sync(0xffffffffu, by, o);
                float oz = __shfl_xor_sync(0xffffffffu, bz, o);
                if (ok > bk) { bk = ok; bx = ox; by = oy; bz = oz; }
            }
            if (lane == 0) {
                scb[c] = bk;
                scx[c] = bx; scy[c] = by; scz[c] = bz;
            }
        }
        __syncthreads();

        // phase C + exchange + winner pick: warp0 only
        if (warp == 0) {
            u64 bk = 0ULL; int bc = 0;
            #pragma unroll
            for (int i = 0; i < NCH / 32; i++) {
                u64 e = scb[lane + 32 * i];
                if (e > bk) { bk = e; bc = lane + 32 * i; }
            }
            #pragma unroll
            for (int o = 16; o > 0; o >>= 1) {
                u64 ok = __shfl_xor_sync(0xffffffffu, bk, o);
                int oc = __shfl_xor_sync(0xffffffffu, bc, o);
                if (ok > bk) { bk = ok; bc = oc; }
            }
            if (lane == 0) {
                u64 xy = ((u64)__float_as_uint(scy[bc]) << 32) |
                         (u64)__float_as_uint(scx[bc]);
                u64 z0 = (u64)__float_as_uint(scz[bc]);
                u32 my_slot = slot_base + (u32)(ph * C + rank) * 24u;
                u32 my_mbar = mbar_base + (u32)ph * 8u;
                #pragma unroll
                for (int r = 0; r < C; r++) {
                    u32 sa = mapa_rank(my_slot, (u32)r);
                    u32 ma = mapa_rank(my_mbar, (u32)r);
                    st_cluster_u64(sa +  0, bk);
                    st_cluster_u64(sa +  8, xy);
                    st_cluster_u64(sa + 16, z0);
                    mbar_arrive_cluster(ma);   // release: orders the 3 stores
                }
            }

            // only warp0 waits on the cluster barrier
            mbar_wait_cluster(mbar_base + (u32)ph * 8u, (u32)par[ph]);

            // pick cluster winner from local slots (redundantly across warp0)
            u64 gb = 0ULL; float nx = 0.f, ny = 0.f, nz = 0.f;
            #pragma unroll
            for (int r = 0; r < C; r++) {
                const char* sp = smem + SM_SLOT + (ph * C + r) * 24;
                u64 key = *(const u64*)(sp + 0);
                u64 xy  = *(const u64*)(sp + 8);
                u64 z0  = *(const u64*)(sp + 16);
                if (key > gb) {
                    gb = key;
                    nx = __uint_as_float((u32)(xy & 0xffffffffull));
                    ny = __uint_as_float((u32)(xy >> 32));
                    nz = __uint_as_float((u32)(z0 & 0xffffffffull));
                }
            }
            if (lane == 0) {
                sbc[0] = nx; sbc[1] = ny; sbc[2] = nz;
                if (rank == 0) {
                    out[(b * K + k) * 3 + 0] = nx;
                    out[(b * K + k) * 3 + 1] = ny;
                    out[(b * K + k) * 3 + 2] = nz;
                }
            }
        }
        par[ph] ^= 1;
        __syncthreads();   // releases sbc to all warps for next iteration
    }

    cluster_sync_asm();   // keep SMEM alive until all peer traffic retired
}

extern "C" void kernel_launch(void* const* d_in, const int* in_sizes, int n_in,
                              void* d_out, int out_size) {
    const float* pts  = (const float*)d_in[0];
    const int*   init = (const int*)d_in[1];
    float*       out  = (float*)d_out;

    cudaFuncSetAttribute(fps_kernel,
                         cudaFuncAttributeMaxDynamicSharedMemorySize, SMEM_TOTAL);

    const int tot = B * N;
    zero_hist_kernel<<<(B * CELLS + 255) / 256, 256>>>();
    cell_hist_kernel<<<(tot + 255) / 256, 256>>>(pts);
    cell_scan_kernel<<<B, 1024>>>();
    scatter_kernel<<<(tot + 255) / 256, 256>>>(pts);
    repack_kernel<<<(tot + 255) / 256, 256>>>();
    chunk_bbox_kernel<<<B * CHB, CH>>>();

    dim3 grid(C, B, 1);
    fps_kernel<<<grid, T, SMEM_TOTAL>>>(pts, init, out);
}

// round 11
// speedup vs baseline: 1.5979x; 1.2152x over previous
#include <cuda_runtime.h>
#include <cooperative_groups.h>
#include <cstdint>

namespace cg = cooperative_groups;
using u64 = unsigned long long;
using u32 = unsigned int;

// Problem constants
constexpr int B = 32;
constexpr int N = 131072;
constexpr int K = 1024;

// Config
constexpr int C     = 4;        // CTAs per batch (cluster)
constexpr int T     = 1024;     // threads per CTA
constexpr int S     = N / C;    // 32768 pts per CTA slice
constexpr int CH    = 128;      // points per chunk (1 float4 round per warp)
constexpr int NCH   = S / CH;   // 256 chunks per CTA
constexpr int CHB   = N / CH;   // 1024 chunks per batch
constexpr int CELLS = 4096;     // 16^3 Morton cells per batch

// Static device scratch (allocation-free)
__device__ __align__(16) float4 g_tmp[B * N];  // scatter target (AoS)
__device__ __align__(16) float  g_x[B * N];    // sorted SoA
__device__ __align__(16) float  g_y[B * N];
__device__ __align__(16) float  g_z[B * N];
__device__ __align__(16) int    g_i[B * N];    // original within-batch index
__device__ int   g_hist[B * CELLS];
__device__ int   g_cur[B * CELLS];
__device__ float g_bbox[B * CHB * 6];

// ---- Morton cell id (4 bits/dim) ----
__device__ __forceinline__ u32 expand3_4(u32 v) {
    return (v & 1u) | ((v & 2u) << 2) | ((v & 4u) << 4) | ((v & 8u) << 6);
}
__device__ __forceinline__ int cell_of(float x, float y, float z) {
    int ix = min(15, max(0, (int)((x + 4.5f) * (16.0f / 9.0f))));
    int iy = min(15, max(0, (int)((y + 4.5f) * (16.0f / 9.0f))));
    int iz = min(15, max(0, (int)((z + 4.5f) * (16.0f / 9.0f))));
    return (int)(expand3_4((u32)ix) | (expand3_4((u32)iy) << 1) |
                 (expand3_4((u32)iz) << 2));
}

// ---- Preprocessing ----
__global__ void zero_hist_kernel() {
    int i = blockIdx.x * blockDim.x + threadIdx.x;
    if (i < B * CELLS) g_hist[i] = 0;
}

__global__ void cell_hist_kernel(const float* __restrict__ pts) {
    int i = blockIdx.x * blockDim.x + threadIdx.x;
    if (i >= B * N) return;
    float x = pts[3 * i], y = pts[3 * i + 1], z = pts[3 * i + 2];
    atomicAdd(&g_hist[(i / N) * CELLS + cell_of(x, y, z)], 1);
}

__global__ void cell_scan_kernel() {   // exclusive scan, one CTA per batch
    __shared__ int wt[32];
    int b = blockIdx.x, t = threadIdx.x;
    int lane = t & 31, w = t >> 5;
    int v[4], s = 0;
    #pragma unroll
    for (int j = 0; j < 4; j++) { v[j] = g_hist[b * CELLS + t * 4 + j]; s += v[j]; }
    int ps = s;
    #pragma unroll
    for (int o = 1; o < 32; o <<= 1) {
        int u = __shfl_up_sync(0xffffffffu, ps, o);
        if (lane >= o) ps += u;
    }
    if (lane == 31) wt[w] = ps;
    __syncthreads();
    if (w == 0) {
        int x = wt[lane];
        #pragma unroll
        for (int o = 1; o < 32; o <<= 1) {
            int u = __shfl_up_sync(0xffffffffu, x, o);
            if (lane >= o) x += u;
        }
        wt[lane] = x;
    }
    __syncthreads();
    int run = (w > 0 ? wt[w - 1] : 0) + (ps - s);
    #pragma unroll
    for (int j = 0; j < 4; j++) { g_cur[b * CELLS + t * 4 + j] = run; run += v[j]; }
}

__global__ void scatter_kernel(const float* __restrict__ pts) {
    int i = blockIdx.x * blockDim.x + threadIdx.x;
    if (i >= B * N) return;
    int b = i / N, j = i - b * N;
    float x = pts[3 * i], y = pts[3 * i + 1], z = pts[3 * i + 2];
    int pos = atomicAdd(&g_cur[b * CELLS + cell_of(x, y, z)], 1);
    g_tmp[b * N + pos] = make_float4(x, y, z, __int_as_float(j));  // one STG.128
}

__global__ void repack_kernel() {      // AoS -> SoA, fully coalesced
    int i = blockIdx.x * blockDim.x + threadIdx.x;
    if (i >= B * N) return;
    float4 p = g_tmp[i];
    g_x[i] = p.x; g_y[i] = p.y; g_z[i] = p.z; g_i[i] = __float_as_int(p.w);
}

__global__ void chunk_bbox_kernel() {   // one 128-thread block per chunk
    __shared__ float rmn[3][4], rmx[3][4];
    int ch = blockIdx.x, t = threadIdx.x;
    int lane = t & 31, w = t >> 5;
    int o = ch * CH + t;
    float x = g_x[o], y = g_y[o], z = g_z[o];
    float mnx = x, mxx = x, mny = y, mxy = y, mnz = z, mxz = z;
    #pragma unroll
    for (int s = 16; s > 0; s >>= 1) {
        mnx = fminf(mnx, __shfl_xor_sync(0xffffffffu, mnx, s));
        mxx = fmaxf(mxx, __shfl_xor_sync(0xffffffffu, mxx, s));
        mny = fminf(mny, __shfl_xor_sync(0xffffffffu, mny, s));
        mxy = fmaxf(mxy, __shfl_xor_sync(0xffffffffu, mxy, s));
        mnz = fminf(mnz, __shfl_xor_sync(0xffffffffu, mnz, s));
        mxz = fmaxf(mxz, __shfl_xor_sync(0xffffffffu, mxz, s));
    }
    if (lane == 0) {
        rmn[0][w] = mnx; rmx[0][w] = mxx;
        rmn[1][w] = mny; rmx[1][w] = mxy;
        rmn[2][w] = mnz; rmx[2][w] = mxz;
    }
    __syncthreads();
    if (t == 0) {
        float a0 = rmn[0][0], b0 = rmx[0][0];
        float a1 = rmn[1][0], b1 = rmx[1][0];
        float a2 = rmn[2][0], b2 = rmx[2][0];
        #pragma unroll
        for (int i = 1; i < 4; i++) {
            a0 = fminf(a0, rmn[0][i]); b0 = fmaxf(b0, rmx[0][i]);
            a1 = fminf(a1, rmn[1][i]); b1 = fmaxf(b1, rmx[1][i]);
            a2 = fminf(a2, rmn[2][i]); b2 = fmaxf(b2, rmx[2][i]);
        }
        float* bb = &g_bbox[ch * 6];
        bb[0] = a0; bb[1] = b0; bb[2] = a1; bb[3] = b1; bb[4] = a2; bb[5] = b2;
    }
}

// ---- Main FPS kernel ----
struct __align__(32) Slot {
    u32 lo, hi;        // packed best: (dist_bits<<32) | ~origidx
    float x, y, z;
    float pad0, pad1, pad2;
};

// SMEM layout (bytes)
constexpr int SM_DIST = 0;                         // S floats  = 131072
constexpr int SM_BOX  = SM_DIST + S * 4;           // NCH*6 f   =   6144
constexpr int SM_CB   = SM_BOX + NCH * 24;         // NCH u64   =   2048
constexpr int SM_CX   = SM_CB + NCH * 8;           // NCH f     =   1024
constexpr int SM_CY   = SM_CX + NCH * 4;
constexpr int SM_CZ   = SM_CY + NCH * 4;
constexpr int SM_WL   = SM_CZ + NCH * 4;           // NCH u32   =   1024
constexpr int SM_WC   = SM_WL + NCH * 4;           // 2 u32 + pad
constexpr int SM_SL   = SM_WC + 16;                // Slot[2][C] = 256
constexpr int SMEM_TOTAL = SM_SL + 2 * C * 32;     // ~143.7 KB

__global__ void __cluster_dims__(C, 1, 1) __launch_bounds__(T, 1)
fps_kernel(const float* __restrict__ pts, const int* __restrict__ init_idx,
           float* __restrict__ out)
{
    extern __shared__ char smem[];
    float4* sd4  = (float4*)(smem + SM_DIST);
    float*  sbox = (float*)(smem + SM_BOX);
    u64*    scb  = (u64*)(smem + SM_CB);
    float*  scx  = (float*)(smem + SM_CX);
    float*  scy  = (float*)(smem + SM_CY);
    float*  scz  = (float*)(smem + SM_CZ);
    u32*    swl  = (u32*)(smem + SM_WL);
    u32*    swc  = (u32*)(smem + SM_WC);
    Slot*   sl   = (Slot*)(smem + SM_SL);

    cg::cluster_group cluster = cg::this_cluster();
    const int rank = blockIdx.x;
    const int b    = blockIdx.y;
    const int t    = threadIdx.x;
    const int warp = t >> 5, lane = t & 31;
    const int gbase = b * N + rank * S;
    const int bbase = (b * CHB + rank * NCH) * 6;

    const float4* __restrict__ gx4 = (const float4*)(g_x + gbase);
    const float4* __restrict__ gy4 = (const float4*)(g_y + gbase);
    const float4* __restrict__ gz4 = (const float4*)(g_z + gbase);
    const int4*   __restrict__ gi4 = (const int4*)(g_i + gbase);

    // ---- init ----
    #pragma unroll
    for (int j = 0; j < S / (4 * T); j++)
        sd4[t + j * T] = make_float4(1e10f, 1e10f, 1e10f, 1e10f);
    for (int i = t; i < NCH * 6; i += T) sbox[i] = g_bbox[bbase + i];
    if (t < NCH) {
        scb[t] = ((u64)__float_as_uint(1e10f)) << 32;   // forces touch at k=1
        scx[t] = 0.f; scy[t] = 0.f; scz[t] = 0.f;
    }
    if (t == 0) { swc[0] = 0; swc[1] = 0; }

    const int idx0 = init_idx[b];
    float lx = pts[3 * (b * N + idx0) + 0];
    float ly = pts[3 * (b * N + idx0) + 1];
    float lz = pts[3 * (b * N + idx0) + 2];
    if (rank == 0 && t == 0) {
        out[(b * K + 0) * 3 + 0] = lx;
        out[(b * K + 0) * 3 + 1] = ly;
        out[(b * K + 0) * 3 + 2] = lz;
    }
    __syncthreads();

    // ---- K-1 sequential iterations ----
    for (int k = 1; k < K; k++) {
        const int ph = k & 1;

        // phase A: reset other-parity counter; bound-check all chunks
        if (t == 0) swc[ph ^ 1] = 0;
        if (t < NCH) {
            const float* bb = &sbox[t * 6];
            float dx = fmaxf(0.0f, fmaxf(bb[0] - lx, lx - bb[1]));
            float dy = fmaxf(0.0f, fmaxf(bb[2] - ly, ly - bb[3]));
            float dz = fmaxf(0.0f, fmaxf(bb[4] - lz, lz - bb[5]));
            float lb2 = __fmaf_rn(dx, dx, __fmaf_rn(dy, dy, dz * dz));
            float cub = __uint_as_float((u32)(scb[t] >> 32));
            if (lb2 * 0.99999f < cub) {             // conservative margin
                u32 p = atomicAdd(&swc[ph], 1u);
                swl[p] = (u32)t;
            }
        }
        __syncthreads();
        const int nw = (int)swc[ph];

        // phase B: one warp per touched chunk (128 pts, SoA coalesced)
        for (int wi = warp; wi < nw; wi += T / 32) {
            int c = (int)swl[wi];
            int f = c * 32 + lane;                  // float4 index, coalesced
            float4 X = gx4[f];
            float4 Y = gy4[f];
            float4 Z = gz4[f];
            int4   I = gi4[f];
            float4 D = sd4[f];
            const float* Xv = (const float*)&X;
            const float* Yv = (const float*)&Y;
            const float* Zv = (const float*)&Z;
            const int*   Iv = (const int*)&I;
            float* Dv = (float*)&D;
            u64 bk = 0ULL;
            float bx = 0.f, by = 0.f, bz = 0.f;
            #pragma unroll
            for (int cc = 0; cc < 4; cc++) {
                float dx = Xv[cc] - lx, dy = Yv[cc] - ly, dz = Zv[cc] - lz;
                float d2 = __fmaf_rn(dx, dx, __fmaf_rn(dy, dy, dz * dz));
                float nd = fminf(Dv[cc], d2);
                Dv[cc] = nd;
                u64 key = (((u64)__float_as_uint(nd)) << 32) |
                          (u32)(~(u32)Iv[cc]);
                if (key > bk) { bk = key; bx = Xv[cc]; by = Yv[cc]; bz = Zv[cc]; }
            }
            sd4[f] = D;
            #pragma unroll
            for (int o = 16; o > 0; o >>= 1) {
                u64   ok = __shfl_xor_sync(0xffffffffu, bk, o);
                float ox = __shfl_xor_sync(0xffffffffu, bx, o);
                float oy = __shfl_xor_sync(0xffffffffu, by, o);
                float oz = __shfl_xor_sync(0xffffffffu, bz, o);
                if (ok > bk) { bk = ok; bx = ox; by = oy; bz = oz; }
            }
            if (lane == 0) {
                scb[c] = bk;
                scx[c] = bx; scy[c] = by; scz[c] = bz;
            }
        }
        __syncthreads();

        // phase C: warp0 reduces 256 chunk keys, pushes best (key+coords)
        if (warp == 0) {
            u64 bk = 0ULL; int bc = 0;
            #pragma unroll
            for (int i = 0; i < NCH / 32; i++) {
                u64 e = scb[lane + 32 * i];
                if (e > bk) { bk = e; bc = lane + 32 * i; }
            }
            #pragma unroll
            for (int o = 16; o > 0; o >>= 1) {
                u64 ok = __shfl_xor_sync(0xffffffffu, bk, o);
                int oc = __shfl_xor_sync(0xffffffffu, bc, o);
                if (ok > bk) { bk = ok; bc = oc; }
            }
            if (lane == 0) {
                Slot* my = &sl[ph * C + rank];
                uint4 w = make_uint4((u32)(bk & 0xffffffffull),
                                     (u32)(bk >> 32),
                                     __float_as_uint(scx[bc]),
                                     __float_as_uint(scy[bc]));
                float cz = scz[bc];
                #pragma unroll
                for (int r = 0; r < C; r++) {
                    Slot* p = (Slot*)cluster.map_shared_rank(my, r);
                    *(uint4*)p = w;
                    p->z = cz;
                }
            }
        }

        cluster.sync();   // orders remote slot stores; acquire for local reads

        // every thread picks the cluster winner from local slots (coords incl.)
        u64 gb = 0ULL;
        float nx = 0.f, ny = 0.f, nz = 0.f;
        #pragma unroll
        for (int r = 0; r < C; r++) {
            const Slot* p = &sl[ph * C + r];
            uint4 w = *(const uint4*)p;
            float z = p->z;
            u64 v = ((u64)w.y << 32) | w.x;
            if (v > gb) {
                gb = v;
                nx = __uint_as_float(w.z);
                ny = __uint_as_float(w.w);
                nz = z;
            }
        }
        lx = nx; ly = ny; lz = nz;

        if (rank == 0 && t == 0) {
            out[(b * K + k) * 3 + 0] = lx;
            out[(b * K + k) * 3 + 1] = ly;
            out[(b * K + k) * 3 + 2] = lz;
        }
    }

    cluster.sync();   // keep SMEM alive until all peer traffic retired
}

extern "C" void kernel_launch(void* const* d_in, const int* in_sizes, int n_in,
                              void* d_out, int out_size) {
    const float* pts  = (const float*)d_in[0];
    const int*   init = (const int*)d_in[1];
    float*       out  = (float*)d_out;

    cudaFuncSetAttribute(fps_kernel,
                         cudaFuncAttributeMaxDynamicSharedMemorySize, SMEM_TOTAL);

    const int tot = B * N;
    zero_hist_kernel<<<(B * CELLS + 255) / 256, 256>>>();
    cell_hist_kernel<<<(tot + 255) / 256, 256>>>(pts);
    cell_scan_kernel<<<B, 1024>>>();
    scatter_kernel<<<(tot + 255) / 256, 256>>>(pts);
    repack_kernel<<<(tot + 255) / 256, 256>>>();
    chunk_bbox_kernel<<<B * CHB, CH>>>();

    dim3 grid(C, B, 1);
    fps_kernel<<<grid, T, SMEM_TOTAL>>>(pts, init, out);
}